// round 9
// baseline (speedup 1.0000x reference)
#include <cuda_runtime.h>
#include <cuda_fp16.h>
#include <cstdint>

// ============================================================================
// Problem dims (fixed by the dataset)
// ============================================================================
#define BB 4
#define TT 256
#define UU 128
#define EE 512
#define DD 640
#define JJ 640
#define VV 1024

// ============================================================================
// Scratch (__device__ globals — allocation-free)
// ============================================================================
__device__ float g_enc_proj[BB * TT * JJ];       // (1024, 640) fp32
__device__ float g_dec_proj[BB * UU * JJ];       // (512, 640)  fp32
__device__ __half g_wt[VV * JJ];                 // W_joint^T (1024, 640) fp16
__device__ __half g_joint[(size_t)BB * TT * UU * JJ];  // tanh joint, fp16 (168MB)

// ============================================================================
// Fused prep kernel: both projections + W_joint transpose in ONE launch
// blocks 0..159   : enc proj  (16 m-tiles x 10 n-tiles)
// blocks 160..239 : dec proj  (8 x 10)
// blocks 240..879 : transpose (32 v-tiles x 20 j-tiles)
// k-chunk 32 with register prefetch: loads of chunk k+1 overlap FMAs of k.
// ============================================================================
__device__ __forceinline__ void proj_gemm_block(
    const float* __restrict__ A, const float* __restrict__ W,
    const float* __restrict__ bias, float* __restrict__ C,
    int K, int m0, int n0, float* As /*64x32*/, float* Ws /*32x64*/) {
    const int tid = threadIdx.x;
    const int tx = tid % 16, ty = tid / 16;
    const int N = JJ;

    // load mapping
    const int ar = tid / 4, ac = (tid % 4) * 8;   // A[ar][ac..ac+7]
    const int wr = tid / 8, wc = (tid % 8) * 8;   // W[wr][wc..wc+7]

    float acc[4][4] = {};

    float4 ra0 = *(const float4*)&A[(size_t)(m0 + ar) * K + ac];
    float4 ra1 = *(const float4*)&A[(size_t)(m0 + ar) * K + ac + 4];
    float4 rw0 = *(const float4*)&W[(size_t)(wr) * N + n0 + wc];
    float4 rw1 = *(const float4*)&W[(size_t)(wr) * N + n0 + wc + 4];

    for (int k0 = 0; k0 < K; k0 += 32) {
        // store current chunk
        *(float4*)&As[ar * 32 + ac] = ra0;
        *(float4*)&As[ar * 32 + ac + 4] = ra1;
        *(float4*)&Ws[wr * 64 + wc] = rw0;
        *(float4*)&Ws[wr * 64 + wc + 4] = rw1;
        __syncthreads();

        // prefetch next chunk (overlaps compute)
        if (k0 + 32 < K) {
            ra0 = *(const float4*)&A[(size_t)(m0 + ar) * K + k0 + 32 + ac];
            ra1 = *(const float4*)&A[(size_t)(m0 + ar) * K + k0 + 32 + ac + 4];
            rw0 = *(const float4*)&W[(size_t)(k0 + 32 + wr) * N + n0 + wc];
            rw1 = *(const float4*)&W[(size_t)(k0 + 32 + wr) * N + n0 + wc + 4];
        }

#pragma unroll
        for (int k = 0; k < 32; k++) {
            float a[4], w[4];
#pragma unroll
            for (int i = 0; i < 4; i++) a[i] = As[(ty * 4 + i) * 32 + k];
#pragma unroll
            for (int j = 0; j < 4; j++) w[j] = Ws[k * 64 + tx * 4 + j];
#pragma unroll
            for (int i = 0; i < 4; i++)
#pragma unroll
                for (int j = 0; j < 4; j++) acc[i][j] = fmaf(a[i], w[j], acc[i][j]);
        }
        __syncthreads();
    }
#pragma unroll
    for (int i = 0; i < 4; i++) {
#pragma unroll
        for (int j = 0; j < 4; j++) {
            int gm = m0 + ty * 4 + i, gn = n0 + tx * 4 + j;
            C[(size_t)gm * N + gn] = acc[i][j] + bias[gn];
        }
    }
}

__global__ void __launch_bounds__(256)
prep_kernel(const float* __restrict__ enc, const float* __restrict__ dec,
            const float* __restrict__ W_enc, const float* __restrict__ b_enc,
            const float* __restrict__ W_dec, const float* __restrict__ b_dec,
            const float* __restrict__ W_joint) {
    __shared__ float As[64 * 32];
    __shared__ float Ws[32 * 64];
    __shared__ float tile[32][33];
    const int bid = blockIdx.x;
    const int tid = threadIdx.x;

    if (bid < 160) {
        proj_gemm_block(enc, W_enc, b_enc, g_enc_proj, EE,
                        (bid / 10) * 64, (bid % 10) * 64, As, Ws);
    } else if (bid < 240) {
        int lb = bid - 160;
        proj_gemm_block(dec, W_dec, b_dec, g_dec_proj, DD,
                        (lb / 10) * 64, (lb % 10) * 64, As, Ws);
    } else {
        int lb = bid - 240;
        const int v0 = (lb & 31) * 32, j0 = (lb >> 5) * 32;
        const int tx = tid & 31, ty = tid >> 5;  // (32, 8)
#pragma unroll
        for (int i = 0; i < 4; i++) {
            int j = j0 + ty + i * 8;
            tile[ty + i * 8][tx] = W_joint[(size_t)j * VV + v0 + tx];
        }
        __syncthreads();
#pragma unroll
        for (int i = 0; i < 4; i++) {
            int v = v0 + ty + i * 8;
            int j = j0 + tx;
            g_wt[(size_t)v * JJ + j] = __float2half_rn(tile[tx][ty + i * 8]);
        }
    }
}

// ============================================================================
// Stage 1c: generate the full tanh joint tensor in fp16 (HBM-write bound)
// ============================================================================
__device__ __forceinline__ float tanh_approx(float x) {
    float y;
    asm("tanh.approx.f32 %0, %1;" : "=f"(y) : "f"(x));
    return y;
}

__global__ void __launch_bounds__(640)
gen_joint_kernel() {
    const int bt = blockIdx.x;
    const int b  = bt >> 8;              // T = 256
    const int j  = threadIdx.x * 4;      // 0..636
    const int us = threadIdx.y;          // 0..3

    float4 e4 = *(const float4*)(g_enc_proj + (size_t)bt * JJ + j);
    __half* outrow = g_joint + ((size_t)bt * UU) * JJ + j;

#pragma unroll 4
    for (int ui = 0; ui < 32; ui++) {
        int u = us + ui * 4;
        float4 d4 = *(const float4*)(g_dec_proj + ((size_t)b * UU + u) * JJ + j);
        __half2 h0 = __floats2half2_rn(tanh_approx(e4.x + d4.x),
                                       tanh_approx(e4.y + d4.y));
        __half2 h1 = __floats2half2_rn(tanh_approx(e4.z + d4.z),
                                       tanh_approx(e4.w + d4.w));
        uint2 pk = { *(uint32_t*)&h0, *(uint32_t*)&h1 };
        *(uint2*)(outrow + (size_t)u * JJ) = pk;
    }
}

// ============================================================================
// Stage 2: pure GEMM via mma.sync (fp16 in, fp32 acc)
//   out[bt,u,v] = sum_j joint[bt,u,j] * wt[v,j] + bias[v]
//
// Grid (4, 1024): CTA = 128 u-rows x 256 vocab cols, 256 threads = 8 warps
// (2 M x 4 N), warp tile 64x64 (squarer -> halved ldsm traffic/MMA).
// 3-stage cp.async pipeline; one barrier per 2048-cycle chunk; 1 CTA/SM.
// ============================================================================
#define KC 64
#define NCHUNK (JJ / KC)                 // 10
#define MT 128                           // M rows per CTA
#define SM_A_BYTES (MT * KC * 2)         // 16 KB
#define SM_B_BYTES (256 * KC * 2)        // 32 KB
#define STAGE_BYTES (SM_A_BYTES + SM_B_BYTES)   // 48 KB
#define NSTAGE 3
#define SM_TOTAL (NSTAGE * STAGE_BYTES)  // 144 KB

__device__ __forceinline__ uint32_t smem_u32(const void* p) {
    uint32_t r;
    asm("{ .reg .u64 t; cvta.to.shared.u64 t, %1; cvt.u32.u64 %0, t; }"
        : "=r"(r) : "l"(p));
    return r;
}

// rows are 128B wide; XOR bits[6:4] with row[2:0] for conflict-free ldmatrix
__device__ __forceinline__ uint32_t swz(uint32_t byte_off) {
    return byte_off ^ ((byte_off >> 3) & 0x70u);
}

__device__ __forceinline__ void cp_async16(uint32_t dst, const void* src) {
    asm volatile("cp.async.cg.shared.global [%0], [%1], 16;"
                 :: "r"(dst), "l"(src));
}
#define CP_COMMIT()  asm volatile("cp.async.commit_group;")
#define CP_WAIT(n)   asm volatile("cp.async.wait_group %0;" :: "n"(n))

__device__ __forceinline__ void ldsm_x4(uint32_t addr, uint32_t& r0, uint32_t& r1,
                                        uint32_t& r2, uint32_t& r3) {
    asm volatile("ldmatrix.sync.aligned.m8n8.x4.shared.b16 {%0,%1,%2,%3}, [%4];"
                 : "=r"(r0), "=r"(r1), "=r"(r2), "=r"(r3) : "r"(addr));
}

__device__ __forceinline__ void mma16816(float* c, const uint32_t* a,
                                         const uint32_t* b) {
    asm volatile(
        "mma.sync.aligned.m16n8k16.row.col.f32.f16.f16.f32 "
        "{%0,%1,%2,%3}, {%4,%5,%6,%7}, {%8,%9}, {%0,%1,%2,%3};"
        : "+f"(c[0]), "+f"(c[1]), "+f"(c[2]), "+f"(c[3])
        : "r"(a[0]), "r"(a[1]), "r"(a[2]), "r"(a[3]), "r"(b[0]), "r"(b[1]));
}

__device__ __forceinline__ void issue_stage(uint32_t sStage, const __half* arow,
                                            int v0, int j0, int tid) {
    const uint32_t sA = sStage;
    const uint32_t sB = sStage + SM_A_BYTES;
    // A: 128 rows x 64 k = 16KB = 1024 x 16B; 4 per thread
#pragma unroll
    for (int r = 0; r < 4; r++) {
        int idx = tid + r * 256;
        int u = idx >> 3, g = idx & 7;
        cp_async16(sA + swz((uint32_t)(u * 128 + g * 16)),
                   arow + (size_t)u * JJ + j0 + g * 8);
    }
    // B: 256 rows x 64 k = 32KB; 8 per thread
#pragma unroll
    for (int r = 0; r < 8; r++) {
        int idx = tid + r * 256;
        int n = idx >> 3, g = idx & 7;
        cp_async16(sB + swz((uint32_t)(n * 128 + g * 16)),
                   g_wt + (size_t)(v0 + n) * JJ + j0 + g * 8);
    }
    CP_COMMIT();
}

__global__ void __launch_bounds__(256, 1)
joint_vocab_kernel(const float* __restrict__ b_joint, float* __restrict__ out) {
    extern __shared__ __align__(128) char smem[];
    const uint32_t s0 = smem_u32(smem);

    const int tid = threadIdx.x;
    const int lane = tid & 31;
    const int wid = tid >> 5;            // 0..7
    const int warp_m = wid & 1;          // m0 = warp_m*64
    const int warp_n = wid >> 1;         // 0..3 -> n0 = warp_n*64

    const int v0 = blockIdx.x * 256;     // vocab tile
    const int bt = blockIdx.y;           // b*T + t

    const __half* arow = g_joint + ((size_t)bt * UU) * JJ;

    // ldmatrix fragment addressing (within a stage)
    const int a_row = warp_m * 64 + (lane & 15);
    const int a_kb  = (lane >> 4) * 16;
    const int b_nrow = warp_n * 64 + ((lane >> 4) << 3) + (lane & 7);
    const int b_kb   = ((lane >> 3) & 1) * 16;

    float acc[4][8][4];
#pragma unroll
    for (int mi = 0; mi < 4; mi++)
#pragma unroll
        for (int ni = 0; ni < 8; ni++)
#pragma unroll
            for (int c = 0; c < 4; c++) acc[mi][ni][c] = 0.0f;

    // ---- prologue: stages 0 and 1 in flight ----
    issue_stage(s0, arow, v0, 0, tid);
    issue_stage(s0 + STAGE_BYTES, arow, v0, KC, tid);
    CP_WAIT(1);   // stage 0 landed
    __syncthreads();

    // ---- main pipeline ----
    for (int kc = 0; kc < NCHUNK; kc++) {
        const uint32_t cur = (uint32_t)(kc % NSTAGE) * STAGE_BYTES;

        // issue stage kc+2 (fire-and-forget during this chunk's MMA)
        if (kc + 2 < NCHUNK)
            issue_stage(s0 + (uint32_t)((kc + 2) % NSTAGE) * STAGE_BYTES,
                        arow, v0, (kc + 2) * KC, tid);

        const uint32_t sAc = s0 + cur;
        const uint32_t sBc = s0 + cur + SM_A_BYTES;
#pragma unroll
        for (int ks = 0; ks < 4; ks++) {
            const int k0b = ks * 32;
            uint32_t a[4][4];
#pragma unroll
            for (int mi = 0; mi < 4; mi++) {
                uint32_t addr = sAc +
                    swz((uint32_t)((a_row + mi * 16) * 128 + k0b + a_kb));
                ldsm_x4(addr, a[mi][0], a[mi][1], a[mi][2], a[mi][3]);
            }
            uint32_t bf[8][2];
#pragma unroll
            for (int nq = 0; nq < 4; nq++) {
                uint32_t addr = sBc +
                    swz((uint32_t)((b_nrow + nq * 16) * 128 + k0b + b_kb));
                ldsm_x4(addr, bf[nq * 2][0], bf[nq * 2][1],
                        bf[nq * 2 + 1][0], bf[nq * 2 + 1][1]);
            }
#pragma unroll
            for (int mi = 0; mi < 4; mi++)
#pragma unroll
                for (int ni = 0; ni < 8; ni++)
                    mma16816(acc[mi][ni], a[mi], bf[ni]);
        }

        // make stage kc+1 visible (it was committed 2 iterations ago)
        if (kc + 2 < NCHUNK)      CP_WAIT(1);
        else if (kc + 1 < NCHUNK) CP_WAIT(0);
        __syncthreads();
    }

    // ---- Epilogue: +bias, write fp32 ----
    {
        const int rowb = warp_m * 64 + (lane >> 2);
        const int colb = warp_n * 64 + (lane & 3) * 2;
        float* outbt = out + ((size_t)bt * UU) * VV + v0;
        const float* bp = b_joint + v0;
#pragma unroll
        for (int ni = 0; ni < 8; ni++) {
            int c_ = colb + ni * 8;
            float2 b2 = *(const float2*)(bp + c_);
#pragma unroll
            for (int mi = 0; mi < 4; mi++) {
                int r_ = rowb + mi * 16;
                float2 o0 = { acc[mi][ni][0] + b2.x, acc[mi][ni][1] + b2.y };
                float2 o1 = { acc[mi][ni][2] + b2.x, acc[mi][ni][3] + b2.y };
                *(float2*)(outbt + (size_t)r_ * VV + c_) = o0;
                *(float2*)(outbt + (size_t)(r_ + 8) * VV + c_) = o1;
            }
        }
    }
}

// ============================================================================
// Launch
// ============================================================================
extern "C" void kernel_launch(void* const* d_in, const int* in_sizes, int n_in,
                              void* d_out, int out_size) {
    const float* enc     = (const float*)d_in[0];
    const float* dec     = (const float*)d_in[1];
    const float* W_enc   = (const float*)d_in[2];
    const float* b_enc   = (const float*)d_in[3];
    const float* W_dec   = (const float*)d_in[4];
    const float* b_dec   = (const float*)d_in[5];
    const float* W_joint = (const float*)d_in[6];
    const float* b_joint = (const float*)d_in[7];
    float* out = (float*)d_out;

    // fused projections + transpose
    prep_kernel<<<880, 256>>>(enc, dec, W_enc, b_enc, W_dec, b_dec, W_joint);

    // full tanh joint tensor (fp16, HBM)
    gen_joint_kernel<<<BB * TT, dim3(160, 4)>>>();

    // pure vocab GEMM
    cudaFuncSetAttribute(joint_vocab_kernel,
                         cudaFuncAttributeMaxDynamicSharedMemorySize, SM_TOTAL);
    joint_vocab_kernel<<<dim3(4, BB * TT), 256, SM_TOTAL>>>(b_joint, out);
}

// round 10
// speedup vs baseline: 1.0967x; 1.0967x over previous
#include <cuda_runtime.h>
#include <cuda_fp16.h>
#include <cstdint>

// ============================================================================
// Problem dims (fixed by the dataset)
// ============================================================================
#define BB 4
#define TT 256
#define UU 128
#define EE 512
#define DD 640
#define JJ 640
#define VV 1024

// ============================================================================
// Scratch (__device__ globals — allocation-free)
// ============================================================================
__device__ float g_enc_proj[BB * TT * JJ];       // (1024, 640) fp32
__device__ float g_dec_proj[BB * UU * JJ];       // (512, 640)  fp32
__device__ __half g_wt[VV * JJ];                 // W_joint^T (1024, 640) fp16
__device__ __half g_joint[(size_t)BB * TT * UU * JJ];  // tanh joint, fp16 (168MB)

// ============================================================================
// Fused prep kernel: both projections + W_joint transpose in ONE launch
// blocks 0..159   : enc proj  (16 m-tiles x 10 n-tiles)
// blocks 160..239 : dec proj  (8 x 10)
// blocks 240..879 : transpose (32 v-tiles x 20 j-tiles)
// k-chunk 32 with register prefetch: loads of chunk k+1 overlap FMAs of k.
// ============================================================================
__device__ __forceinline__ void proj_gemm_block(
    const float* __restrict__ A, const float* __restrict__ W,
    const float* __restrict__ bias, float* __restrict__ C,
    int K, int m0, int n0, float* As /*64x32*/, float* Ws /*32x64*/) {
    const int tid = threadIdx.x;
    const int tx = tid % 16, ty = tid / 16;
    const int N = JJ;

    const int ar = tid / 4, ac = (tid % 4) * 8;   // A[ar][ac..ac+7]
    const int wr = tid / 8, wc = (tid % 8) * 8;   // W[wr][wc..wc+7]

    float acc[4][4] = {};

    float4 ra0 = *(const float4*)&A[(size_t)(m0 + ar) * K + ac];
    float4 ra1 = *(const float4*)&A[(size_t)(m0 + ar) * K + ac + 4];
    float4 rw0 = *(const float4*)&W[(size_t)(wr) * N + n0 + wc];
    float4 rw1 = *(const float4*)&W[(size_t)(wr) * N + n0 + wc + 4];

    for (int k0 = 0; k0 < K; k0 += 32) {
        *(float4*)&As[ar * 32 + ac] = ra0;
        *(float4*)&As[ar * 32 + ac + 4] = ra1;
        *(float4*)&Ws[wr * 64 + wc] = rw0;
        *(float4*)&Ws[wr * 64 + wc + 4] = rw1;
        __syncthreads();

        if (k0 + 32 < K) {
            ra0 = *(const float4*)&A[(size_t)(m0 + ar) * K + k0 + 32 + ac];
            ra1 = *(const float4*)&A[(size_t)(m0 + ar) * K + k0 + 32 + ac + 4];
            rw0 = *(const float4*)&W[(size_t)(k0 + 32 + wr) * N + n0 + wc];
            rw1 = *(const float4*)&W[(size_t)(k0 + 32 + wr) * N + n0 + wc + 4];
        }

#pragma unroll
        for (int k = 0; k < 32; k++) {
            float a[4], w[4];
#pragma unroll
            for (int i = 0; i < 4; i++) a[i] = As[(ty * 4 + i) * 32 + k];
#pragma unroll
            for (int j = 0; j < 4; j++) w[j] = Ws[k * 64 + tx * 4 + j];
#pragma unroll
            for (int i = 0; i < 4; i++)
#pragma unroll
                for (int j = 0; j < 4; j++) acc[i][j] = fmaf(a[i], w[j], acc[i][j]);
        }
        __syncthreads();
    }
#pragma unroll
    for (int i = 0; i < 4; i++) {
#pragma unroll
        for (int j = 0; j < 4; j++) {
            int gm = m0 + ty * 4 + i, gn = n0 + tx * 4 + j;
            C[(size_t)gm * N + gn] = acc[i][j] + bias[gn];
        }
    }
}

__global__ void __launch_bounds__(256)
prep_kernel(const float* __restrict__ enc, const float* __restrict__ dec,
            const float* __restrict__ W_enc, const float* __restrict__ b_enc,
            const float* __restrict__ W_dec, const float* __restrict__ b_dec,
            const float* __restrict__ W_joint) {
    __shared__ float As[64 * 32];
    __shared__ float Ws[32 * 64];
    __shared__ float tile[32][33];
    const int bid = blockIdx.x;
    const int tid = threadIdx.x;

    if (bid < 160) {
        proj_gemm_block(enc, W_enc, b_enc, g_enc_proj, EE,
                        (bid / 10) * 64, (bid % 10) * 64, As, Ws);
    } else if (bid < 240) {
        int lb = bid - 160;
        proj_gemm_block(dec, W_dec, b_dec, g_dec_proj, DD,
                        (lb / 10) * 64, (lb % 10) * 64, As, Ws);
    } else {
        int lb = bid - 240;
        const int v0 = (lb & 31) * 32, j0 = (lb >> 5) * 32;
        const int tx = tid & 31, ty = tid >> 5;  // (32, 8)
#pragma unroll
        for (int i = 0; i < 4; i++) {
            int j = j0 + ty + i * 8;
            tile[ty + i * 8][tx] = W_joint[(size_t)j * VV + v0 + tx];
        }
        __syncthreads();
#pragma unroll
        for (int i = 0; i < 4; i++) {
            int v = v0 + ty + i * 8;
            int j = j0 + tx;
            g_wt[(size_t)v * JJ + j] = __float2half_rn(tile[tx][ty + i * 8]);
        }
    }
}

// ============================================================================
// Stage 1c: generate the full tanh joint tensor in fp16 (HBM-write bound)
// ============================================================================
__device__ __forceinline__ float tanh_approx(float x) {
    float y;
    asm("tanh.approx.f32 %0, %1;" : "=f"(y) : "f"(x));
    return y;
}

__global__ void __launch_bounds__(640)
gen_joint_kernel() {
    const int bt = blockIdx.x;
    const int b  = bt >> 8;              // T = 256
    const int j  = threadIdx.x * 4;      // 0..636
    const int us = threadIdx.y;          // 0..3

    float4 e4 = *(const float4*)(g_enc_proj + (size_t)bt * JJ + j);
    __half* outrow = g_joint + ((size_t)bt * UU) * JJ + j;

#pragma unroll 4
    for (int ui = 0; ui < 32; ui++) {
        int u = us + ui * 4;
        float4 d4 = *(const float4*)(g_dec_proj + ((size_t)b * UU + u) * JJ + j);
        __half2 h0 = __floats2half2_rn(tanh_approx(e4.x + d4.x),
                                       tanh_approx(e4.y + d4.y));
        __half2 h1 = __floats2half2_rn(tanh_approx(e4.z + d4.z),
                                       tanh_approx(e4.w + d4.w));
        uint2 pk = { *(uint32_t*)&h0, *(uint32_t*)&h1 };
        *(uint2*)(outrow + (size_t)u * JJ) = pk;
    }
}

// ============================================================================
// Stage 2: pure GEMM via mma.sync (fp16 in, fp32 acc)
//   out[bt,u,v] = sum_j joint[bt,u,j] * wt[v,j] + bias[v]
//
// Grid (8, 1024): CTA = 64 u-rows x 256 vocab cols, 128 threads = 4 warps,
// warp tile 64x64 (1M x 4N) -> B ldsm traffic HALVED vs 8x(32x64).
// 2-stage cp.async; 2 CTAs co-resident per SM (desynchronized barrier
// domains hide each other's sync windows).
// ============================================================================
#define KC 64
#define NCHUNK (JJ / KC)                 // 10
#define MT 64                            // M rows per CTA
#define SM_A_BYTES (MT * KC * 2)         // 8 KB
#define SM_B_BYTES (256 * KC * 2)        // 32 KB
#define STAGE_BYTES (SM_A_BYTES + SM_B_BYTES)   // 40 KB
#define SM_TOTAL (2 * STAGE_BYTES)       // 80 KB (x2 CTAs = 160 KB/SM)

__device__ __forceinline__ uint32_t smem_u32(const void* p) {
    uint32_t r;
    asm("{ .reg .u64 t; cvta.to.shared.u64 t, %1; cvt.u32.u64 %0, t; }"
        : "=r"(r) : "l"(p));
    return r;
}

// rows are 128B wide; XOR bits[6:4] with row[2:0] for conflict-free ldmatrix
__device__ __forceinline__ uint32_t swz(uint32_t byte_off) {
    return byte_off ^ ((byte_off >> 3) & 0x70u);
}

__device__ __forceinline__ void cp_async16(uint32_t dst, const void* src) {
    asm volatile("cp.async.cg.shared.global [%0], [%1], 16;"
                 :: "r"(dst), "l"(src));
}
#define CP_COMMIT()  asm volatile("cp.async.commit_group;")
#define CP_WAIT0()   asm volatile("cp.async.wait_group 0;")

__device__ __forceinline__ void ldsm_x4(uint32_t addr, uint32_t& r0, uint32_t& r1,
                                        uint32_t& r2, uint32_t& r3) {
    asm volatile("ldmatrix.sync.aligned.m8n8.x4.shared.b16 {%0,%1,%2,%3}, [%4];"
                 : "=r"(r0), "=r"(r1), "=r"(r2), "=r"(r3) : "r"(addr));
}

__device__ __forceinline__ void mma16816(float* c, const uint32_t* a,
                                         const uint32_t* b) {
    asm volatile(
        "mma.sync.aligned.m16n8k16.row.col.f32.f16.f16.f32 "
        "{%0,%1,%2,%3}, {%4,%5,%6,%7}, {%8,%9}, {%0,%1,%2,%3};"
        : "+f"(c[0]), "+f"(c[1]), "+f"(c[2]), "+f"(c[3])
        : "r"(a[0]), "r"(a[1]), "r"(a[2]), "r"(a[3]), "r"(b[0]), "r"(b[1]));
}

__device__ __forceinline__ void issue_stage(uint32_t sStage, const __half* arow,
                                            int v0, int j0, int tid) {
    const uint32_t sA = sStage;
    const uint32_t sB = sStage + SM_A_BYTES;
    // A: 64 rows x 64 k = 8KB = 512 x 16B; 4 per thread (128 thr)
#pragma unroll
    for (int r = 0; r < 4; r++) {
        int idx = tid + r * 128;
        int u = idx >> 3, g = idx & 7;
        cp_async16(sA + swz((uint32_t)(u * 128 + g * 16)),
                   arow + (size_t)u * JJ + j0 + g * 8);
    }
    // B: 256 rows x 64 k = 32KB = 2048 x 16B; 16 per thread
#pragma unroll
    for (int r = 0; r < 16; r++) {
        int idx = tid + r * 128;
        int n = idx >> 3, g = idx & 7;
        cp_async16(sB + swz((uint32_t)(n * 128 + g * 16)),
                   g_wt + (size_t)(v0 + n) * JJ + j0 + g * 8);
    }
    CP_COMMIT();
}

__global__ void __launch_bounds__(128, 2)
joint_vocab_kernel(const float* __restrict__ b_joint, float* __restrict__ out) {
    extern __shared__ __align__(128) char smem[];
    const uint32_t s0 = smem_u32(smem);

    const int tid = threadIdx.x;
    const int lane = tid & 31;
    const int warp_n = tid >> 5;         // 0..3 -> n0 = warp_n*64 (M covered fully)

    const int bx = blockIdx.x;           // 0..7
    const int v0 = (bx & 3) * 256;       // vocab tile
    const int u0 = (bx >> 2) * MT;       // u half
    const int bt = blockIdx.y;           // b*T + t

    const __half* arow = g_joint + ((size_t)bt * UU + u0) * JJ;

    // ldmatrix fragment addressing (within a stage)
    const int a_row = lane & 15;                          // + mi*16
    const int a_kb  = (lane >> 4) * 16;
    const int b_nrow = warp_n * 64 + ((lane >> 4) << 3) + (lane & 7);
    const int b_kb   = ((lane >> 3) & 1) * 16;

    float acc[4][8][4];
#pragma unroll
    for (int mi = 0; mi < 4; mi++)
#pragma unroll
        for (int ni = 0; ni < 8; ni++)
#pragma unroll
            for (int c = 0; c < 4; c++) acc[mi][ni][c] = 0.0f;

    // ---- prologue: stage 0 ----
    issue_stage(s0, arow, v0, 0, tid);
    CP_WAIT0();
    __syncthreads();

    // ---- main pipeline (2-stage) ----
    for (int kc = 0; kc < NCHUNK; kc++) {
        const uint32_t cur = (uint32_t)(kc & 1) * STAGE_BYTES;
        const bool has_next = (kc + 1) < NCHUNK;

        // issue stage kc+1 (fire-and-forget during this chunk's MMA)
        if (has_next)
            issue_stage(s0 + (uint32_t)((kc + 1) & 1) * STAGE_BYTES,
                        arow, v0, (kc + 1) * KC, tid);

        const uint32_t sAc = s0 + cur;
        const uint32_t sBc = s0 + cur + SM_A_BYTES;
#pragma unroll
        for (int ks = 0; ks < 4; ks++) {
            const int k0b = ks * 32;
            uint32_t a[4][4];
#pragma unroll
            for (int mi = 0; mi < 4; mi++) {
                uint32_t addr = sAc +
                    swz((uint32_t)((a_row + mi * 16) * 128 + k0b + a_kb));
                ldsm_x4(addr, a[mi][0], a[mi][1], a[mi][2], a[mi][3]);
            }
            uint32_t bf[8][2];
#pragma unroll
            for (int nq = 0; nq < 4; nq++) {
                uint32_t addr = sBc +
                    swz((uint32_t)((b_nrow + nq * 16) * 128 + k0b + b_kb));
                ldsm_x4(addr, bf[nq * 2][0], bf[nq * 2][1],
                        bf[nq * 2 + 1][0], bf[nq * 2 + 1][1]);
            }
#pragma unroll
            for (int mi = 0; mi < 4; mi++)
#pragma unroll
                for (int ni = 0; ni < 8; ni++)
                    mma16816(acc[mi][ni], a[mi], bf[ni]);
        }

        if (has_next) CP_WAIT0();
        __syncthreads();
    }

    // ---- Epilogue: +bias, write fp32 ----
    {
        const int rowb = lane >> 2;
        const int colb = warp_n * 64 + (lane & 3) * 2;
        float* outbt = out + ((size_t)bt * UU + u0) * VV + v0;
        const float* bp = b_joint + v0;
#pragma unroll
        for (int ni = 0; ni < 8; ni++) {
            int c_ = colb + ni * 8;
            float2 b2 = *(const float2*)(bp + c_);
#pragma unroll
            for (int mi = 0; mi < 4; mi++) {
                int r_ = rowb + mi * 16;
                float2 o0 = { acc[mi][ni][0] + b2.x, acc[mi][ni][1] + b2.y };
                float2 o1 = { acc[mi][ni][2] + b2.x, acc[mi][ni][3] + b2.y };
                *(float2*)(outbt + (size_t)r_ * VV + c_) = o0;
                *(float2*)(outbt + (size_t)(r_ + 8) * VV + c_) = o1;
            }
        }
    }
}

// ============================================================================
// Launch
// ============================================================================
extern "C" void kernel_launch(void* const* d_in, const int* in_sizes, int n_in,
                              void* d_out, int out_size) {
    const float* enc     = (const float*)d_in[0];
    const float* dec     = (const float*)d_in[1];
    const float* W_enc   = (const float*)d_in[2];
    const float* b_enc   = (const float*)d_in[3];
    const float* W_dec   = (const float*)d_in[4];
    const float* b_dec   = (const float*)d_in[5];
    const float* W_joint = (const float*)d_in[6];
    const float* b_joint = (const float*)d_in[7];
    float* out = (float*)d_out;

    // fused projections + transpose
    prep_kernel<<<880, 256>>>(enc, dec, W_enc, b_enc, W_dec, b_dec, W_joint);

    // full tanh joint tensor (fp16, HBM)
    gen_joint_kernel<<<BB * TT, dim3(160, 4)>>>();

    // pure vocab GEMM
    cudaFuncSetAttribute(joint_vocab_kernel,
                         cudaFuncAttributeMaxDynamicSharedMemorySize, SM_TOTAL);
    joint_vocab_kernel<<<dim3(8, BB * TT), 128, SM_TOTAL>>>(b_joint, out);
}

// round 11
// speedup vs baseline: 1.0967x; 1.0001x over previous
#include <cuda_runtime.h>
#include <cuda_fp16.h>
#include <cstdint>

// ============================================================================
// Problem dims (fixed by the dataset)
// ============================================================================
#define BB 4
#define TT 256
#define UU 128
#define EE 512
#define DD 640
#define JJ 640
#define VV 1024

// ============================================================================
// Scratch (__device__ globals — allocation-free)
// ============================================================================
__device__ float g_enc_proj[BB * TT * JJ];       // (1024, 640) fp32
__device__ float g_dec_proj[BB * UU * JJ];       // (512, 640)  fp32
__device__ __half g_wt[VV * JJ];                 // W_joint^T (1024, 640) fp16
__device__ __half g_joint[(size_t)BB * TT * UU * JJ];  // tanh joint, fp16 (168MB)

// ============================================================================
// Fused prep kernel: both projections + W_joint transpose in ONE launch
// blocks 0..159   : enc proj  (16 m-tiles x 10 n-tiles)
// blocks 160..239 : dec proj  (8 x 10)
// blocks 240..879 : transpose (32 v-tiles x 20 j-tiles)
// k-chunk 32 with register prefetch: loads of chunk k+1 overlap FMAs of k.
// ============================================================================
__device__ __forceinline__ void proj_gemm_block(
    const float* __restrict__ A, const float* __restrict__ W,
    const float* __restrict__ bias, float* __restrict__ C,
    int K, int m0, int n0, float* As /*64x32*/, float* Ws /*32x64*/) {
    const int tid = threadIdx.x;
    const int tx = tid % 16, ty = tid / 16;
    const int N = JJ;

    const int ar = tid / 4, ac = (tid % 4) * 8;   // A[ar][ac..ac+7]
    const int wr = tid / 8, wc = (tid % 8) * 8;   // W[wr][wc..wc+7]

    float acc[4][4] = {};

    float4 ra0 = *(const float4*)&A[(size_t)(m0 + ar) * K + ac];
    float4 ra1 = *(const float4*)&A[(size_t)(m0 + ar) * K + ac + 4];
    float4 rw0 = *(const float4*)&W[(size_t)(wr) * N + n0 + wc];
    float4 rw1 = *(const float4*)&W[(size_t)(wr) * N + n0 + wc + 4];

    for (int k0 = 0; k0 < K; k0 += 32) {
        *(float4*)&As[ar * 32 + ac] = ra0;
        *(float4*)&As[ar * 32 + ac + 4] = ra1;
        *(float4*)&Ws[wr * 64 + wc] = rw0;
        *(float4*)&Ws[wr * 64 + wc + 4] = rw1;
        __syncthreads();

        if (k0 + 32 < K) {
            ra0 = *(const float4*)&A[(size_t)(m0 + ar) * K + k0 + 32 + ac];
            ra1 = *(const float4*)&A[(size_t)(m0 + ar) * K + k0 + 32 + ac + 4];
            rw0 = *(const float4*)&W[(size_t)(k0 + 32 + wr) * N + n0 + wc];
            rw1 = *(const float4*)&W[(size_t)(k0 + 32 + wr) * N + n0 + wc + 4];
        }

#pragma unroll
        for (int k = 0; k < 32; k++) {
            float a[4], w[4];
#pragma unroll
            for (int i = 0; i < 4; i++) a[i] = As[(ty * 4 + i) * 32 + k];
#pragma unroll
            for (int j = 0; j < 4; j++) w[j] = Ws[k * 64 + tx * 4 + j];
#pragma unroll
            for (int i = 0; i < 4; i++)
#pragma unroll
                for (int j = 0; j < 4; j++) acc[i][j] = fmaf(a[i], w[j], acc[i][j]);
        }
        __syncthreads();
    }
#pragma unroll
    for (int i = 0; i < 4; i++) {
#pragma unroll
        for (int j = 0; j < 4; j++) {
            int gm = m0 + ty * 4 + i, gn = n0 + tx * 4 + j;
            C[(size_t)gm * N + gn] = acc[i][j] + bias[gn];
        }
    }
}

__global__ void __launch_bounds__(256)
prep_kernel(const float* __restrict__ enc, const float* __restrict__ dec,
            const float* __restrict__ W_enc, const float* __restrict__ b_enc,
            const float* __restrict__ W_dec, const float* __restrict__ b_dec,
            const float* __restrict__ W_joint) {
    __shared__ float As[64 * 32];
    __shared__ float Ws[32 * 64];
    __shared__ float tile[32][33];
    const int bid = blockIdx.x;
    const int tid = threadIdx.x;

    if (bid < 160) {
        proj_gemm_block(enc, W_enc, b_enc, g_enc_proj, EE,
                        (bid / 10) * 64, (bid % 10) * 64, As, Ws);
    } else if (bid < 240) {
        int lb = bid - 160;
        proj_gemm_block(dec, W_dec, b_dec, g_dec_proj, DD,
                        (lb / 10) * 64, (lb % 10) * 64, As, Ws);
    } else {
        int lb = bid - 240;
        const int v0 = (lb & 31) * 32, j0 = (lb >> 5) * 32;
        const int tx = tid & 31, ty = tid >> 5;  // (32, 8)
#pragma unroll
        for (int i = 0; i < 4; i++) {
            int j = j0 + ty + i * 8;
            tile[ty + i * 8][tx] = W_joint[(size_t)j * VV + v0 + tx];
        }
        __syncthreads();
#pragma unroll
        for (int i = 0; i < 4; i++) {
            int v = v0 + ty + i * 8;
            int j = j0 + tx;
            g_wt[(size_t)v * JJ + j] = __float2half_rn(tile[tx][ty + i * 8]);
        }
    }
}

// ============================================================================
// Stage 1c: generate the full tanh joint tensor in fp16 (HBM-write bound)
// ============================================================================
__device__ __forceinline__ float tanh_approx(float x) {
    float y;
    asm("tanh.approx.f32 %0, %1;" : "=f"(y) : "f"(x));
    return y;
}

__global__ void __launch_bounds__(640)
gen_joint_kernel() {
    const int bt = blockIdx.x;
    const int b  = bt >> 8;              // T = 256
    const int j  = threadIdx.x * 4;      // 0..636
    const int us = threadIdx.y;          // 0..3

    float4 e4 = *(const float4*)(g_enc_proj + (size_t)bt * JJ + j);
    __half* outrow = g_joint + ((size_t)bt * UU) * JJ + j;

#pragma unroll 4
    for (int ui = 0; ui < 32; ui++) {
        int u = us + ui * 4;
        float4 d4 = *(const float4*)(g_dec_proj + ((size_t)b * UU + u) * JJ + j);
        __half2 h0 = __floats2half2_rn(tanh_approx(e4.x + d4.x),
                                       tanh_approx(e4.y + d4.y));
        __half2 h1 = __floats2half2_rn(tanh_approx(e4.z + d4.z),
                                       tanh_approx(e4.w + d4.w));
        uint2 pk = { *(uint32_t*)&h0, *(uint32_t*)&h1 };
        *(uint2*)(outrow + (size_t)u * JJ) = pk;
    }
}

// ============================================================================
// Stage 2: pure GEMM via mma.sync (fp16 in, fp32 acc)
//   out[bt,u,v] = sum_j joint[bt,u,j] * wt[v,j] + bias[v]
//
// Grid (8, 1024): CTA = 64 u-rows x 256 vocab cols, 128 threads = 4 warps,
// warp tile 64x64 (1M x 4N) -> B ldsm traffic HALVED vs 8x(32x64).
// 2-stage cp.async; 2 CTAs co-resident per SM (desynchronized barrier
// domains hide each other's sync windows).
// ============================================================================
#define KC 64
#define NCHUNK (JJ / KC)                 // 10
#define MT 64                            // M rows per CTA
#define SM_A_BYTES (MT * KC * 2)         // 8 KB
#define SM_B_BYTES (256 * KC * 2)        // 32 KB
#define STAGE_BYTES (SM_A_BYTES + SM_B_BYTES)   // 40 KB
#define SM_TOTAL (2 * STAGE_BYTES)       // 80 KB (x2 CTAs = 160 KB/SM)

__device__ __forceinline__ uint32_t smem_u32(const void* p) {
    uint32_t r;
    asm("{ .reg .u64 t; cvta.to.shared.u64 t, %1; cvt.u32.u64 %0, t; }"
        : "=r"(r) : "l"(p));
    return r;
}

// rows are 128B wide; XOR bits[6:4] with row[2:0] for conflict-free ldmatrix
__device__ __forceinline__ uint32_t swz(uint32_t byte_off) {
    return byte_off ^ ((byte_off >> 3) & 0x70u);
}

__device__ __forceinline__ void cp_async16(uint32_t dst, const void* src) {
    asm volatile("cp.async.cg.shared.global [%0], [%1], 16;"
                 :: "r"(dst), "l"(src));
}
#define CP_COMMIT()  asm volatile("cp.async.commit_group;")
#define CP_WAIT0()   asm volatile("cp.async.wait_group 0;")

__device__ __forceinline__ void ldsm_x4(uint32_t addr, uint32_t& r0, uint32_t& r1,
                                        uint32_t& r2, uint32_t& r3) {
    asm volatile("ldmatrix.sync.aligned.m8n8.x4.shared.b16 {%0,%1,%2,%3}, [%4];"
                 : "=r"(r0), "=r"(r1), "=r"(r2), "=r"(r3) : "r"(addr));
}

__device__ __forceinline__ void mma16816(float* c, const uint32_t* a,
                                         const uint32_t* b) {
    asm volatile(
        "mma.sync.aligned.m16n8k16.row.col.f32.f16.f16.f32 "
        "{%0,%1,%2,%3}, {%4,%5,%6,%7}, {%8,%9}, {%0,%1,%2,%3};"
        : "+f"(c[0]), "+f"(c[1]), "+f"(c[2]), "+f"(c[3])
        : "r"(a[0]), "r"(a[1]), "r"(a[2]), "r"(a[3]), "r"(b[0]), "r"(b[1]));
}

__device__ __forceinline__ void issue_stage(uint32_t sStage, const __half* arow,
                                            int v0, int j0, int tid) {
    const uint32_t sA = sStage;
    const uint32_t sB = sStage + SM_A_BYTES;
    // A: 64 rows x 64 k = 8KB = 512 x 16B; 4 per thread (128 thr)
#pragma unroll
    for (int r = 0; r < 4; r++) {
        int idx = tid + r * 128;
        int u = idx >> 3, g = idx & 7;
        cp_async16(sA + swz((uint32_t)(u * 128 + g * 16)),
                   arow + (size_t)u * JJ + j0 + g * 8);
    }
    // B: 256 rows x 64 k = 32KB = 2048 x 16B; 16 per thread
#pragma unroll
    for (int r = 0; r < 16; r++) {
        int idx = tid + r * 128;
        int n = idx >> 3, g = idx & 7;
        cp_async16(sB + swz((uint32_t)(n * 128 + g * 16)),
                   g_wt + (size_t)(v0 + n) * JJ + j0 + g * 8);
    }
    CP_COMMIT();
}

__global__ void __launch_bounds__(128, 2)
joint_vocab_kernel(const float* __restrict__ b_joint, float* __restrict__ out) {
    extern __shared__ __align__(128) char smem[];
    const uint32_t s0 = smem_u32(smem);

    const int tid = threadIdx.x;
    const int lane = tid & 31;
    const int warp_n = tid >> 5;         // 0..3 -> n0 = warp_n*64 (M covered fully)

    const int bx = blockIdx.x;           // 0..7
    const int v0 = (bx & 3) * 256;       // vocab tile
    const int u0 = (bx >> 2) * MT;       // u half
    const int bt = blockIdx.y;           // b*T + t

    const __half* arow = g_joint + ((size_t)bt * UU + u0) * JJ;

    // ldmatrix fragment addressing (within a stage)
    const int a_row = lane & 15;                          // + mi*16
    const int a_kb  = (lane >> 4) * 16;
    const int b_nrow = warp_n * 64 + ((lane >> 4) << 3) + (lane & 7);
    const int b_kb   = ((lane >> 3) & 1) * 16;

    float acc[4][8][4];
#pragma unroll
    for (int mi = 0; mi < 4; mi++)
#pragma unroll
        for (int ni = 0; ni < 8; ni++)
#pragma unroll
            for (int c = 0; c < 4; c++) acc[mi][ni][c] = 0.0f;

    // ---- prologue: stage 0 ----
    issue_stage(s0, arow, v0, 0, tid);
    CP_WAIT0();
    __syncthreads();

    // ---- main pipeline (2-stage) ----
    for (int kc = 0; kc < NCHUNK; kc++) {
        const uint32_t cur = (uint32_t)(kc & 1) * STAGE_BYTES;
        const bool has_next = (kc + 1) < NCHUNK;

        // issue stage kc+1 (fire-and-forget during this chunk's MMA)
        if (has_next)
            issue_stage(s0 + (uint32_t)((kc + 1) & 1) * STAGE_BYTES,
                        arow, v0, (kc + 1) * KC, tid);

        const uint32_t sAc = s0 + cur;
        const uint32_t sBc = s0 + cur + SM_A_BYTES;
#pragma unroll
        for (int ks = 0; ks < 4; ks++) {
            const int k0b = ks * 32;
            uint32_t a[4][4];
#pragma unroll
            for (int mi = 0; mi < 4; mi++) {
                uint32_t addr = sAc +
                    swz((uint32_t)((a_row + mi * 16) * 128 + k0b + a_kb));
                ldsm_x4(addr, a[mi][0], a[mi][1], a[mi][2], a[mi][3]);
            }
            uint32_t bf[8][2];
#pragma unroll
            for (int nq = 0; nq < 4; nq++) {
                uint32_t addr = sBc +
                    swz((uint32_t)((b_nrow + nq * 16) * 128 + k0b + b_kb));
                ldsm_x4(addr, bf[nq * 2][0], bf[nq * 2][1],
                        bf[nq * 2 + 1][0], bf[nq * 2 + 1][1]);
            }
#pragma unroll
            for (int mi = 0; mi < 4; mi++)
#pragma unroll
                for (int ni = 0; ni < 8; ni++)
                    mma16816(acc[mi][ni], a[mi], bf[ni]);
        }

        if (has_next) CP_WAIT0();
        __syncthreads();
    }

    // ---- Epilogue: +bias, write fp32 ----
    {
        const int rowb = lane >> 2;
        const int colb = warp_n * 64 + (lane & 3) * 2;
        float* outbt = out + ((size_t)bt * UU + u0) * VV + v0;
        const float* bp = b_joint + v0;
#pragma unroll
        for (int ni = 0; ni < 8; ni++) {
            int c_ = colb + ni * 8;
            float2 b2 = *(const float2*)(bp + c_);
#pragma unroll
            for (int mi = 0; mi < 4; mi++) {
                int r_ = rowb + mi * 16;
                float2 o0 = { acc[mi][ni][0] + b2.x, acc[mi][ni][1] + b2.y };
                float2 o1 = { acc[mi][ni][2] + b2.x, acc[mi][ni][3] + b2.y };
                *(float2*)(outbt + (size_t)r_ * VV + c_) = o0;
                *(float2*)(outbt + (size_t)(r_ + 8) * VV + c_) = o1;
            }
        }
    }
}

// ============================================================================
// Launch
// ============================================================================
extern "C" void kernel_launch(void* const* d_in, const int* in_sizes, int n_in,
                              void* d_out, int out_size) {
    const float* enc     = (const float*)d_in[0];
    const float* dec     = (const float*)d_in[1];
    const float* W_enc   = (const float*)d_in[2];
    const float* b_enc   = (const float*)d_in[3];
    const float* W_dec   = (const float*)d_in[4];
    const float* b_dec   = (const float*)d_in[5];
    const float* W_joint = (const float*)d_in[6];
    const float* b_joint = (const float*)d_in[7];
    float* out = (float*)d_out;

    // fused projections + transpose
    prep_kernel<<<880, 256>>>(enc, dec, W_enc, b_enc, W_dec, b_dec, W_joint);

    // full tanh joint tensor (fp16, HBM)
    gen_joint_kernel<<<BB * TT, dim3(160, 4)>>>();

    // pure vocab GEMM
    cudaFuncSetAttribute(joint_vocab_kernel,
                         cudaFuncAttributeMaxDynamicSharedMemorySize, SM_TOTAL);
    joint_vocab_kernel<<<dim3(8, BB * TT), 128, SM_TOTAL>>>(b_joint, out);
}

// round 12
// speedup vs baseline: 1.0988x; 1.0018x over previous
#include <cuda_runtime.h>
#include <cuda_fp16.h>
#include <cstdint>

// ============================================================================
// Problem dims (fixed by the dataset)
// ============================================================================
#define BB 4
#define TT 256
#define UU 128
#define EE 512
#define DD 640
#define JJ 640
#define VV 1024

// ============================================================================
// Scratch (__device__ globals — allocation-free)
// ============================================================================
__device__ float g_enc_proj[BB * TT * JJ];       // (1024, 640) fp32
__device__ float g_dec_proj[BB * UU * JJ];       // (512, 640)  fp32
__device__ __half g_wt[VV * JJ];                 // W_joint^T (1024, 640) fp16
__device__ __half g_joint[(size_t)BB * TT * UU * JJ];  // tanh joint, fp16 (168MB)

// ============================================================================
// Fused prep kernel: both projections + W_joint transpose in ONE launch
// blocks 0..159   : enc proj  (16 m-tiles x 10 n-tiles)
// blocks 160..239 : dec proj  (8 x 10)
// blocks 240..879 : transpose (32 v-tiles x 20 j-tiles)
// k-chunk 32, register prefetch + DOUBLE-BUFFERED smem: ONE barrier per chunk.
// ============================================================================
__device__ __forceinline__ void proj_gemm_block(
    const float* __restrict__ A, const float* __restrict__ W,
    const float* __restrict__ bias, float* __restrict__ C,
    int K, int m0, int n0, float* As /*2x64x32*/, float* Ws /*2x32x64*/) {
    const int tid = threadIdx.x;
    const int tx = tid % 16, ty = tid / 16;
    const int N = JJ;

    const int ar = tid / 4, ac = (tid % 4) * 8;   // A[ar][ac..ac+7]
    const int wr = tid / 8, wc = (tid % 8) * 8;   // W[wr][wc..wc+7]

    float acc[4][4] = {};

    float4 ra0 = *(const float4*)&A[(size_t)(m0 + ar) * K + ac];
    float4 ra1 = *(const float4*)&A[(size_t)(m0 + ar) * K + ac + 4];
    float4 rw0 = *(const float4*)&W[(size_t)(wr) * N + n0 + wc];
    float4 rw1 = *(const float4*)&W[(size_t)(wr) * N + n0 + wc + 4];

    int buf = 0;
    for (int k0 = 0; k0 < K; k0 += 32) {
        float* Ab = As + buf * (64 * 32);
        float* Wb = Ws + buf * (32 * 64);
        *(float4*)&Ab[ar * 32 + ac] = ra0;
        *(float4*)&Ab[ar * 32 + ac + 4] = ra1;
        *(float4*)&Wb[wr * 64 + wc] = rw0;
        *(float4*)&Wb[wr * 64 + wc + 4] = rw1;
        __syncthreads();   // single barrier: next stores go to the other buffer

        if (k0 + 32 < K) {
            ra0 = *(const float4*)&A[(size_t)(m0 + ar) * K + k0 + 32 + ac];
            ra1 = *(const float4*)&A[(size_t)(m0 + ar) * K + k0 + 32 + ac + 4];
            rw0 = *(const float4*)&W[(size_t)(k0 + 32 + wr) * N + n0 + wc];
            rw1 = *(const float4*)&W[(size_t)(k0 + 32 + wr) * N + n0 + wc + 4];
        }

#pragma unroll
        for (int k = 0; k < 32; k++) {
            float a[4], w[4];
#pragma unroll
            for (int i = 0; i < 4; i++) a[i] = Ab[(ty * 4 + i) * 32 + k];
#pragma unroll
            for (int j = 0; j < 4; j++) w[j] = Wb[k * 64 + tx * 4 + j];
#pragma unroll
            for (int i = 0; i < 4; i++)
#pragma unroll
                for (int j = 0; j < 4; j++) acc[i][j] = fmaf(a[i], w[j], acc[i][j]);
        }
        buf ^= 1;
    }
#pragma unroll
    for (int i = 0; i < 4; i++) {
#pragma unroll
        for (int j = 0; j < 4; j++) {
            int gm = m0 + ty * 4 + i, gn = n0 + tx * 4 + j;
            C[(size_t)gm * N + gn] = acc[i][j] + bias[gn];
        }
    }
}

__global__ void __launch_bounds__(256)
prep_kernel(const float* __restrict__ enc, const float* __restrict__ dec,
            const float* __restrict__ W_enc, const float* __restrict__ b_enc,
            const float* __restrict__ W_dec, const float* __restrict__ b_dec,
            const float* __restrict__ W_joint) {
    __shared__ float As[2 * 64 * 32];
    __shared__ float Ws[2 * 32 * 64];
    __shared__ float tile[32][33];
    const int bid = blockIdx.x;
    const int tid = threadIdx.x;

    if (bid < 160) {
        proj_gemm_block(enc, W_enc, b_enc, g_enc_proj, EE,
                        (bid / 10) * 64, (bid % 10) * 64, As, Ws);
    } else if (bid < 240) {
        int lb = bid - 160;
        proj_gemm_block(dec, W_dec, b_dec, g_dec_proj, DD,
                        (lb / 10) * 64, (lb % 10) * 64, As, Ws);
    } else {
        int lb = bid - 240;
        const int v0 = (lb & 31) * 32, j0 = (lb >> 5) * 32;
        const int tx = tid & 31, ty = tid >> 5;  // (32, 8)
#pragma unroll
        for (int i = 0; i < 4; i++) {
            int j = j0 + ty + i * 8;
            tile[ty + i * 8][tx] = W_joint[(size_t)j * VV + v0 + tx];
        }
        __syncthreads();
#pragma unroll
        for (int i = 0; i < 4; i++) {
            int v = v0 + ty + i * 8;
            int j = j0 + tx;
            g_wt[(size_t)v * JJ + j] = __float2half_rn(tile[tx][ty + i * 8]);
        }
    }
}

// ============================================================================
// Stage 1c: generate the full tanh joint tensor in fp16 (HBM-write bound)
// ============================================================================
__device__ __forceinline__ float tanh_approx(float x) {
    float y;
    asm("tanh.approx.f32 %0, %1;" : "=f"(y) : "f"(x));
    return y;
}

__global__ void __launch_bounds__(640)
gen_joint_kernel() {
    const int bt = blockIdx.x;
    const int b  = bt >> 8;              // T = 256
    const int j  = threadIdx.x * 4;      // 0..636
    const int us = threadIdx.y;          // 0..3

    float4 e4 = *(const float4*)(g_enc_proj + (size_t)bt * JJ + j);
    __half* outrow = g_joint + ((size_t)bt * UU) * JJ + j;

#pragma unroll 4
    for (int ui = 0; ui < 32; ui++) {
        int u = us + ui * 4;
        float4 d4 = *(const float4*)(g_dec_proj + ((size_t)b * UU + u) * JJ + j);
        __half2 h0 = __floats2half2_rn(tanh_approx(e4.x + d4.x),
                                       tanh_approx(e4.y + d4.y));
        __half2 h1 = __floats2half2_rn(tanh_approx(e4.z + d4.z),
                                       tanh_approx(e4.w + d4.w));
        uint2 pk = { *(uint32_t*)&h0, *(uint32_t*)&h1 };
        *(uint2*)(outrow + (size_t)u * JJ) = pk;
    }
}

// ============================================================================
// Stage 2: pure GEMM via mma.sync (fp16 in, fp32 acc)
//   out[bt,u,v] = sum_j joint[bt,u,j] * wt[v,j] + bias[v]
//
// Grid (8, 1024): CTA = 64 u-rows x 256 vocab cols, 128 threads = 4 warps,
// warp tile 64x64 (1M x 4N). 2-stage cp.async; 2 CTAs co-resident per SM.
// Output written with evict-first (.cs) stores: never re-read, keeps
// g_joint/g_wt resident in L2 for the co-scheduled vocab CTAs.
// ============================================================================
#define KC 64
#define NCHUNK (JJ / KC)                 // 10
#define MT 64                            // M rows per CTA
#define SM_A_BYTES (MT * KC * 2)         // 8 KB
#define SM_B_BYTES (256 * KC * 2)        // 32 KB
#define STAGE_BYTES (SM_A_BYTES + SM_B_BYTES)   // 40 KB
#define SM_TOTAL (2 * STAGE_BYTES)       // 80 KB (x2 CTAs = 160 KB/SM)

__device__ __forceinline__ uint32_t smem_u32(const void* p) {
    uint32_t r;
    asm("{ .reg .u64 t; cvta.to.shared.u64 t, %1; cvt.u32.u64 %0, t; }"
        : "=r"(r) : "l"(p));
    return r;
}

// rows are 128B wide; XOR bits[6:4] with row[2:0] for conflict-free ldmatrix
__device__ __forceinline__ uint32_t swz(uint32_t byte_off) {
    return byte_off ^ ((byte_off >> 3) & 0x70u);
}

__device__ __forceinline__ void cp_async16(uint32_t dst, const void* src) {
    asm volatile("cp.async.cg.shared.global [%0], [%1], 16;"
                 :: "r"(dst), "l"(src));
}
#define CP_COMMIT()  asm volatile("cp.async.commit_group;")
#define CP_WAIT0()   asm volatile("cp.async.wait_group 0;")

__device__ __forceinline__ void ldsm_x4(uint32_t addr, uint32_t& r0, uint32_t& r1,
                                        uint32_t& r2, uint32_t& r3) {
    asm volatile("ldmatrix.sync.aligned.m8n8.x4.shared.b16 {%0,%1,%2,%3}, [%4];"
                 : "=r"(r0), "=r"(r1), "=r"(r2), "=r"(r3) : "r"(addr));
}

__device__ __forceinline__ void mma16816(float* c, const uint32_t* a,
                                         const uint32_t* b) {
    asm volatile(
        "mma.sync.aligned.m16n8k16.row.col.f32.f16.f16.f32 "
        "{%0,%1,%2,%3}, {%4,%5,%6,%7}, {%8,%9}, {%0,%1,%2,%3};"
        : "+f"(c[0]), "+f"(c[1]), "+f"(c[2]), "+f"(c[3])
        : "r"(a[0]), "r"(a[1]), "r"(a[2]), "r"(a[3]), "r"(b[0]), "r"(b[1]));
}

__device__ __forceinline__ void stcs_f2(float* p, float2 v) {
    asm volatile("st.global.cs.v2.f32 [%0], {%1, %2};"
                 :: "l"(p), "f"(v.x), "f"(v.y) : "memory");
}

__device__ __forceinline__ void issue_stage(uint32_t sStage, const __half* arow,
                                            int v0, int j0, int tid) {
    const uint32_t sA = sStage;
    const uint32_t sB = sStage + SM_A_BYTES;
    // A: 64 rows x 64 k = 8KB = 512 x 16B; 4 per thread (128 thr)
#pragma unroll
    for (int r = 0; r < 4; r++) {
        int idx = tid + r * 128;
        int u = idx >> 3, g = idx & 7;
        cp_async16(sA + swz((uint32_t)(u * 128 + g * 16)),
                   arow + (size_t)u * JJ + j0 + g * 8);
    }
    // B: 256 rows x 64 k = 32KB = 2048 x 16B; 16 per thread
#pragma unroll
    for (int r = 0; r < 16; r++) {
        int idx = tid + r * 128;
        int n = idx >> 3, g = idx & 7;
        cp_async16(sB + swz((uint32_t)(n * 128 + g * 16)),
                   g_wt + (size_t)(v0 + n) * JJ + j0 + g * 8);
    }
    CP_COMMIT();
}

__global__ void __launch_bounds__(128, 2)
joint_vocab_kernel(const float* __restrict__ b_joint, float* __restrict__ out) {
    extern __shared__ __align__(128) char smem[];
    const uint32_t s0 = smem_u32(smem);

    const int tid = threadIdx.x;
    const int lane = tid & 31;
    const int warp_n = tid >> 5;         // 0..3 -> n0 = warp_n*64 (M covered fully)

    const int bx = blockIdx.x;           // 0..7
    const int v0 = (bx & 3) * 256;       // vocab tile
    const int u0 = (bx >> 2) * MT;       // u half
    const int bt = blockIdx.y;           // b*T + t

    const __half* arow = g_joint + ((size_t)bt * UU + u0) * JJ;

    // ldmatrix fragment addressing (within a stage)
    const int a_row = lane & 15;                          // + mi*16
    const int a_kb  = (lane >> 4) * 16;
    const int b_nrow = warp_n * 64 + ((lane >> 4) << 3) + (lane & 7);
    const int b_kb   = ((lane >> 3) & 1) * 16;

    float acc[4][8][4];
#pragma unroll
    for (int mi = 0; mi < 4; mi++)
#pragma unroll
        for (int ni = 0; ni < 8; ni++)
#pragma unroll
            for (int c = 0; c < 4; c++) acc[mi][ni][c] = 0.0f;

    // ---- prologue: stage 0 ----
    issue_stage(s0, arow, v0, 0, tid);
    CP_WAIT0();
    __syncthreads();

    // ---- main pipeline (2-stage) ----
    for (int kc = 0; kc < NCHUNK; kc++) {
        const uint32_t cur = (uint32_t)(kc & 1) * STAGE_BYTES;
        const bool has_next = (kc + 1) < NCHUNK;

        // issue stage kc+1 (fire-and-forget during this chunk's MMA)
        if (has_next)
            issue_stage(s0 + (uint32_t)((kc + 1) & 1) * STAGE_BYTES,
                        arow, v0, (kc + 1) * KC, tid);

        const uint32_t sAc = s0 + cur;
        const uint32_t sBc = s0 + cur + SM_A_BYTES;
#pragma unroll
        for (int ks = 0; ks < 4; ks++) {
            const int k0b = ks * 32;
            uint32_t a[4][4];
#pragma unroll
            for (int mi = 0; mi < 4; mi++) {
                uint32_t addr = sAc +
                    swz((uint32_t)((a_row + mi * 16) * 128 + k0b + a_kb));
                ldsm_x4(addr, a[mi][0], a[mi][1], a[mi][2], a[mi][3]);
            }
            uint32_t bf[8][2];
#pragma unroll
            for (int nq = 0; nq < 4; nq++) {
                uint32_t addr = sBc +
                    swz((uint32_t)((b_nrow + nq * 16) * 128 + k0b + b_kb));
                ldsm_x4(addr, bf[nq * 2][0], bf[nq * 2][1],
                        bf[nq * 2 + 1][0], bf[nq * 2 + 1][1]);
            }
#pragma unroll
            for (int mi = 0; mi < 4; mi++)
#pragma unroll
                for (int ni = 0; ni < 8; ni++)
                    mma16816(acc[mi][ni], a[mi], bf[ni]);
        }

        if (has_next) CP_WAIT0();
        __syncthreads();
    }

    // ---- Epilogue: +bias, evict-first fp32 stores ----
    {
        const int rowb = lane >> 2;
        const int colb = warp_n * 64 + (lane & 3) * 2;
        float* outbt = out + ((size_t)bt * UU + u0) * VV + v0;
        const float* bp = b_joint + v0;
#pragma unroll
        for (int ni = 0; ni < 8; ni++) {
            int c_ = colb + ni * 8;
            float2 b2 = *(const float2*)(bp + c_);
#pragma unroll
            for (int mi = 0; mi < 4; mi++) {
                int r_ = rowb + mi * 16;
                float2 o0 = { acc[mi][ni][0] + b2.x, acc[mi][ni][1] + b2.y };
                float2 o1 = { acc[mi][ni][2] + b2.x, acc[mi][ni][3] + b2.y };
                stcs_f2(outbt + (size_t)r_ * VV + c_, o0);
                stcs_f2(outbt + (size_t)(r_ + 8) * VV + c_, o1);
            }
        }
    }
}

// ============================================================================
// Launch
// ============================================================================
extern "C" void kernel_launch(void* const* d_in, const int* in_sizes, int n_in,
                              void* d_out, int out_size) {
    const float* enc     = (const float*)d_in[0];
    const float* dec     = (const float*)d_in[1];
    const float* W_enc   = (const float*)d_in[2];
    const float* b_enc   = (const float*)d_in[3];
    const float* W_dec   = (const float*)d_in[4];
    const float* b_dec   = (const float*)d_in[5];
    const float* W_joint = (const float*)d_in[6];
    const float* b_joint = (const float*)d_in[7];
    float* out = (float*)d_out;

    // fused projections + transpose
    prep_kernel<<<880, 256>>>(enc, dec, W_enc, b_enc, W_dec, b_dec, W_joint);

    // full tanh joint tensor (fp16, HBM)
    gen_joint_kernel<<<BB * TT, dim3(160, 4)>>>();

    // pure vocab GEMM
    cudaFuncSetAttribute(joint_vocab_kernel,
                         cudaFuncAttributeMaxDynamicSharedMemorySize, SM_TOTAL);
    joint_vocab_kernel<<<dim3(8, BB * TT), 128, SM_TOTAL>>>(b_joint, out);
}

// round 13
// speedup vs baseline: 1.1448x; 1.0419x over previous
#include <cuda_runtime.h>
#include <cuda_fp16.h>
#include <cstdint>

// ============================================================================
// Problem dims (fixed by the dataset)
// ============================================================================
#define BB 4
#define TT 256
#define UU 128
#define EE 512
#define DD 640
#define JJ 640
#define VV 1024

// ============================================================================
// Scratch (__device__ globals — allocation-free)
// ============================================================================
__device__ float g_enc_proj[BB * TT * JJ];       // (1024, 640) fp32
__device__ float g_dec_proj[BB * UU * JJ];       // (512, 640)  fp32
__device__ __half g_wt[VV * JJ];                 // W_joint^T (1024, 640) fp16
__device__ __half g_joint[(size_t)BB * TT * UU * JJ];  // tanh joint, fp16 (168MB)

// ============================================================================
// Fused prep kernel: both projections + W_joint transpose in ONE launch
// ============================================================================
__device__ __forceinline__ void proj_gemm_block(
    const float* __restrict__ A, const float* __restrict__ W,
    const float* __restrict__ bias, float* __restrict__ C,
    int K, int m0, int n0, float* As /*2x64x32*/, float* Ws /*2x32x64*/) {
    const int tid = threadIdx.x;
    const int tx = tid % 16, ty = tid / 16;
    const int N = JJ;

    const int ar = tid / 4, ac = (tid % 4) * 8;   // A[ar][ac..ac+7]
    const int wr = tid / 8, wc = (tid % 8) * 8;   // W[wr][wc..wc+7]

    float acc[4][4] = {};

    float4 ra0 = *(const float4*)&A[(size_t)(m0 + ar) * K + ac];
    float4 ra1 = *(const float4*)&A[(size_t)(m0 + ar) * K + ac + 4];
    float4 rw0 = *(const float4*)&W[(size_t)(wr) * N + n0 + wc];
    float4 rw1 = *(const float4*)&W[(size_t)(wr) * N + n0 + wc + 4];

    int buf = 0;
    for (int k0 = 0; k0 < K; k0 += 32) {
        float* Ab = As + buf * (64 * 32);
        float* Wb = Ws + buf * (32 * 64);
        *(float4*)&Ab[ar * 32 + ac] = ra0;
        *(float4*)&Ab[ar * 32 + ac + 4] = ra1;
        *(float4*)&Wb[wr * 64 + wc] = rw0;
        *(float4*)&Wb[wr * 64 + wc + 4] = rw1;
        __syncthreads();

        if (k0 + 32 < K) {
            ra0 = *(const float4*)&A[(size_t)(m0 + ar) * K + k0 + 32 + ac];
            ra1 = *(const float4*)&A[(size_t)(m0 + ar) * K + k0 + 32 + ac + 4];
            rw0 = *(const float4*)&W[(size_t)(k0 + 32 + wr) * N + n0 + wc];
            rw1 = *(const float4*)&W[(size_t)(k0 + 32 + wr) * N + n0 + wc + 4];
        }

#pragma unroll
        for (int k = 0; k < 32; k++) {
            float a[4], w[4];
#pragma unroll
            for (int i = 0; i < 4; i++) a[i] = Ab[(ty * 4 + i) * 32 + k];
#pragma unroll
            for (int j = 0; j < 4; j++) w[j] = Wb[k * 64 + tx * 4 + j];
#pragma unroll
            for (int i = 0; i < 4; i++)
#pragma unroll
                for (int j = 0; j < 4; j++) acc[i][j] = fmaf(a[i], w[j], acc[i][j]);
        }
        buf ^= 1;
    }
#pragma unroll
    for (int i = 0; i < 4; i++) {
#pragma unroll
        for (int j = 0; j < 4; j++) {
            int gm = m0 + ty * 4 + i, gn = n0 + tx * 4 + j;
            C[(size_t)gm * N + gn] = acc[i][j] + bias[gn];
        }
    }
}

__global__ void __launch_bounds__(256)
prep_kernel(const float* __restrict__ enc, const float* __restrict__ dec,
            const float* __restrict__ W_enc, const float* __restrict__ b_enc,
            const float* __restrict__ W_dec, const float* __restrict__ b_dec,
            const float* __restrict__ W_joint) {
    __shared__ float As[2 * 64 * 32];
    __shared__ float Ws[2 * 32 * 64];
    __shared__ float tile[32][33];
    const int bid = blockIdx.x;
    const int tid = threadIdx.x;

    if (bid < 160) {
        proj_gemm_block(enc, W_enc, b_enc, g_enc_proj, EE,
                        (bid / 10) * 64, (bid % 10) * 64, As, Ws);
    } else if (bid < 240) {
        int lb = bid - 160;
        proj_gemm_block(dec, W_dec, b_dec, g_dec_proj, DD,
                        (lb / 10) * 64, (lb % 10) * 64, As, Ws);
    } else {
        int lb = bid - 240;
        const int v0 = (lb & 31) * 32, j0 = (lb >> 5) * 32;
        const int tx = tid & 31, ty = tid >> 5;  // (32, 8)
#pragma unroll
        for (int i = 0; i < 4; i++) {
            int j = j0 + ty + i * 8;
            tile[ty + i * 8][tx] = W_joint[(size_t)j * VV + v0 + tx];
        }
        __syncthreads();
#pragma unroll
        for (int i = 0; i < 4; i++) {
            int v = v0 + ty + i * 8;
            int j = j0 + tx;
            g_wt[(size_t)v * JJ + j] = __float2half_rn(tile[tx][ty + i * 8]);
        }
    }
}

// ============================================================================
// Stage 1c: generate the full tanh joint tensor in fp16 (HBM-write bound)
// ============================================================================
__device__ __forceinline__ float tanh_approx(float x) {
    float y;
    asm("tanh.approx.f32 %0, %1;" : "=f"(y) : "f"(x));
    return y;
}

__global__ void __launch_bounds__(640)
gen_joint_kernel() {
    const int bt = blockIdx.x;
    const int b  = bt >> 8;              // T = 256
    const int j  = threadIdx.x * 4;      // 0..636
    const int us = threadIdx.y;          // 0..3

    float4 e4 = *(const float4*)(g_enc_proj + (size_t)bt * JJ + j);
    __half* outrow = g_joint + ((size_t)bt * UU) * JJ + j;

#pragma unroll 4
    for (int ui = 0; ui < 32; ui++) {
        int u = us + ui * 4;
        float4 d4 = *(const float4*)(g_dec_proj + ((size_t)b * UU + u) * JJ + j);
        __half2 h0 = __floats2half2_rn(tanh_approx(e4.x + d4.x),
                                       tanh_approx(e4.y + d4.y));
        __half2 h1 = __floats2half2_rn(tanh_approx(e4.z + d4.z),
                                       tanh_approx(e4.w + d4.w));
        uint2 pk = { *(uint32_t*)&h0, *(uint32_t*)&h1 };
        *(uint2*)(outrow + (size_t)u * JJ) = pk;
    }
}

// ============================================================================
// Stage 2: pure GEMM via mma.sync (fp16 in, fp32 acc)
//   out[bt,u,v] = sum_j joint[bt,u,j] * wt[v,j] + bias[v]
//
// Grid (8, 1024): CTA = 128 u-rows x 128 vocab cols, 128 threads = 4 warps
// (2M x 2N at 64x64). NT=MT=128 minimizes total L2 cp traffic
// (A (V/NT)x168MB + B (Mtot/MT)x1.25MB: 3.3GB -> 2.6GB vs (256,64)).
// 3-stage cp.async (32KB/stage) x 2 co-resident CTAs per SM.
// ============================================================================
#define KC 64
#define NCHUNK (JJ / KC)                 // 10
#define MT 128                           // M rows per CTA
#define NT 128                           // vocab cols per CTA
#define SM_A_BYTES (MT * KC * 2)         // 16 KB
#define SM_B_BYTES (NT * KC * 2)         // 16 KB
#define STAGE_BYTES (SM_A_BYTES + SM_B_BYTES)   // 32 KB
#define NSTAGE 3
#define SM_TOTAL (NSTAGE * STAGE_BYTES)  // 96 KB (x2 CTAs = 192 KB/SM)

__device__ __forceinline__ uint32_t smem_u32(const void* p) {
    uint32_t r;
    asm("{ .reg .u64 t; cvta.to.shared.u64 t, %1; cvt.u32.u64 %0, t; }"
        : "=r"(r) : "l"(p));
    return r;
}

// rows are 128B wide; XOR bits[6:4] with row[2:0] for conflict-free ldmatrix
__device__ __forceinline__ uint32_t swz(uint32_t byte_off) {
    return byte_off ^ ((byte_off >> 3) & 0x70u);
}

__device__ __forceinline__ void cp_async16(uint32_t dst, const void* src) {
    asm volatile("cp.async.cg.shared.global [%0], [%1], 16;"
                 :: "r"(dst), "l"(src));
}
#define CP_COMMIT()  asm volatile("cp.async.commit_group;")
#define CP_WAIT(n)   asm volatile("cp.async.wait_group %0;" :: "n"(n))

__device__ __forceinline__ void ldsm_x4(uint32_t addr, uint32_t& r0, uint32_t& r1,
                                        uint32_t& r2, uint32_t& r3) {
    asm volatile("ldmatrix.sync.aligned.m8n8.x4.shared.b16 {%0,%1,%2,%3}, [%4];"
                 : "=r"(r0), "=r"(r1), "=r"(r2), "=r"(r3) : "r"(addr));
}

__device__ __forceinline__ void mma16816(float* c, const uint32_t* a,
                                         const uint32_t* b) {
    asm volatile(
        "mma.sync.aligned.m16n8k16.row.col.f32.f16.f16.f32 "
        "{%0,%1,%2,%3}, {%4,%5,%6,%7}, {%8,%9}, {%0,%1,%2,%3};"
        : "+f"(c[0]), "+f"(c[1]), "+f"(c[2]), "+f"(c[3])
        : "r"(a[0]), "r"(a[1]), "r"(a[2]), "r"(a[3]), "r"(b[0]), "r"(b[1]));
}

__device__ __forceinline__ void stcs_f2(float* p, float2 v) {
    asm volatile("st.global.cs.v2.f32 [%0], {%1, %2};"
                 :: "l"(p), "f"(v.x), "f"(v.y) : "memory");
}

__device__ __forceinline__ void issue_stage(uint32_t sStage, const __half* arow,
                                            int v0, int j0, int tid) {
    const uint32_t sA = sStage;
    const uint32_t sB = sStage + SM_A_BYTES;
    // A: 128 rows x 64 k = 16KB = 1024 x 16B; 8 per thread (128 thr)
#pragma unroll
    for (int r = 0; r < 8; r++) {
        int idx = tid + r * 128;
        int u = idx >> 3, g = idx & 7;
        cp_async16(sA + swz((uint32_t)(u * 128 + g * 16)),
                   arow + (size_t)u * JJ + j0 + g * 8);
    }
    // B: 128 rows x 64 k = 16KB = 1024 x 16B; 8 per thread
#pragma unroll
    for (int r = 0; r < 8; r++) {
        int idx = tid + r * 128;
        int n = idx >> 3, g = idx & 7;
        cp_async16(sB + swz((uint32_t)(n * 128 + g * 16)),
                   g_wt + (size_t)(v0 + n) * JJ + j0 + g * 8);
    }
    CP_COMMIT();
}

__global__ void __launch_bounds__(128, 2)
joint_vocab_kernel(const float* __restrict__ b_joint, float* __restrict__ out) {
    extern __shared__ __align__(128) char smem[];
    const uint32_t s0 = smem_u32(smem);

    const int tid = threadIdx.x;
    const int lane = tid & 31;
    const int wid = tid >> 5;            // 0..3
    const int warp_m = wid & 1;          // m0 = warp_m*64
    const int warp_n = wid >> 1;         // 0..1 -> n0 = warp_n*64

    const int v0 = blockIdx.x * NT;      // vocab tile
    const int bt = blockIdx.y;           // b*T + t

    const __half* arow = g_joint + ((size_t)bt * UU) * JJ;

    // ldmatrix fragment addressing (within a stage)
    const int a_row = warp_m * 64 + (lane & 15);          // + mi*16
    const int a_kb  = (lane >> 4) * 16;
    const int b_nrow = warp_n * 64 + ((lane >> 4) << 3) + (lane & 7);
    const int b_kb   = ((lane >> 3) & 1) * 16;

    float acc[4][8][4];
#pragma unroll
    for (int mi = 0; mi < 4; mi++)
#pragma unroll
        for (int ni = 0; ni < 8; ni++)
#pragma unroll
            for (int c = 0; c < 4; c++) acc[mi][ni][c] = 0.0f;

    // ---- prologue: stages 0 and 1 in flight ----
    issue_stage(s0, arow, v0, 0, tid);
    issue_stage(s0 + STAGE_BYTES, arow, v0, KC, tid);
    CP_WAIT(1);   // stage 0 landed
    __syncthreads();

    // ---- main pipeline (3-stage) ----
    for (int kc = 0; kc < NCHUNK; kc++) {
        const uint32_t cur = (uint32_t)(kc % NSTAGE) * STAGE_BYTES;

        // issue stage kc+2 (fire-and-forget during this chunk's MMA)
        if (kc + 2 < NCHUNK)
            issue_stage(s0 + (uint32_t)((kc + 2) % NSTAGE) * STAGE_BYTES,
                        arow, v0, (kc + 2) * KC, tid);

        const uint32_t sAc = s0 + cur;
        const uint32_t sBc = s0 + cur + SM_A_BYTES;
#pragma unroll
        for (int ks = 0; ks < 4; ks++) {
            const int k0b = ks * 32;
            uint32_t a[4][4];
#pragma unroll
            for (int mi = 0; mi < 4; mi++) {
                uint32_t addr = sAc +
                    swz((uint32_t)((a_row + mi * 16) * 128 + k0b + a_kb));
                ldsm_x4(addr, a[mi][0], a[mi][1], a[mi][2], a[mi][3]);
            }
            uint32_t bf[8][2];
#pragma unroll
            for (int nq = 0; nq < 4; nq++) {
                uint32_t addr = sBc +
                    swz((uint32_t)((b_nrow + nq * 16) * 128 + k0b + b_kb));
                ldsm_x4(addr, bf[nq * 2][0], bf[nq * 2][1],
                        bf[nq * 2 + 1][0], bf[nq * 2 + 1][1]);
            }
#pragma unroll
            for (int mi = 0; mi < 4; mi++)
#pragma unroll
                for (int ni = 0; ni < 8; ni++)
                    mma16816(acc[mi][ni], a[mi], bf[ni]);
        }

        // stage kc+1 must be visible before next iteration consumes it
        if (kc + 2 < NCHUNK)      CP_WAIT(1);
        else if (kc + 1 < NCHUNK) CP_WAIT(0);
        __syncthreads();
    }

    // ---- Epilogue: +bias, evict-first fp32 stores ----
    {
        const int rowb = warp_m * 64 + (lane >> 2);
        const int colb = warp_n * 64 + (lane & 3) * 2;
        float* outbt = out + ((size_t)bt * UU) * VV + v0;
        const float* bp = b_joint + v0;
#pragma unroll
        for (int ni = 0; ni < 8; ni++) {
            int c_ = colb + ni * 8;
            float2 b2 = *(const float2*)(bp + c_);
#pragma unroll
            for (int mi = 0; mi < 4; mi++) {
                int r_ = rowb + mi * 16;
                float2 o0 = { acc[mi][ni][0] + b2.x, acc[mi][ni][1] + b2.y };
                float2 o1 = { acc[mi][ni][2] + b2.x, acc[mi][ni][3] + b2.y };
                stcs_f2(outbt + (size_t)r_ * VV + c_, o0);
                stcs_f2(outbt + (size_t)(r_ + 8) * VV + c_, o1);
            }
        }
    }
}

// ============================================================================
// Launch
// ============================================================================
extern "C" void kernel_launch(void* const* d_in, const int* in_sizes, int n_in,
                              void* d_out, int out_size) {
    const float* enc     = (const float*)d_in[0];
    const float* dec     = (const float*)d_in[1];
    const float* W_enc   = (const float*)d_in[2];
    const float* b_enc   = (const float*)d_in[3];
    const float* W_dec   = (const float*)d_in[4];
    const float* b_dec   = (const float*)d_in[5];
    const float* W_joint = (const float*)d_in[6];
    const float* b_joint = (const float*)d_in[7];
    float* out = (float*)d_out;

    // fused projections + transpose
    prep_kernel<<<880, 256>>>(enc, dec, W_enc, b_enc, W_dec, b_dec, W_joint);

    // full tanh joint tensor (fp16, HBM)
    gen_joint_kernel<<<BB * TT, dim3(160, 4)>>>();

    // pure vocab GEMM
    cudaFuncSetAttribute(joint_vocab_kernel,
                         cudaFuncAttributeMaxDynamicSharedMemorySize, SM_TOTAL);
    joint_vocab_kernel<<<dim3(VV / NT, BB * TT), 128, SM_TOTAL>>>(b_joint, out);
}